// round 3
// baseline (speedup 1.0000x reference)
#include <cuda_runtime.h>

#define BATCH 4
#define CHN   1029
#define HH    80
#define WW    80
#define NROI  1024
#define DD    21
#define PH    7
#define PW    7
#define SCALE 0.0625f

// Direct PSROI pooling: one thread per output element (n, d, ph, pw).
//
// Numerics matched to XLA's lowering of the reference:
//  - rnd(v) = floor(v + 0.5): all adds exact (values < 2048 with small addends)
//  - * SPATIAL_SCALE (1/16): exact
//  - roi_ew - roi_sw: exact (multiples of 1/16)
//  - bin = roi * (1/7): XLA rewrites "divide by constant" into "multiply by
//    reciprocal"; (1.0f/7.0f) folds to the correctly-rounded f32 reciprocal.
//  - edges: separate round-to-nearest mul then add (uncontracted elementwise).
// Bin sums computed directly from the input (near-exact), avoiding any SAT
// rounding-order question entirely.
__global__ __launch_bounds__(256) void psroi_direct_kernel(
    const float* __restrict__ in,       // (4,1029,80,80)
    const float* __restrict__ rois,     // (1024,5)
    float* __restrict__ out) {          // (1024,21,7,7)

    const int idx = blockIdx.x * blockDim.x + threadIdx.x;
    const int total = NROI * DD * PH * PW;
    if (idx >= total) return;

    const int pw = idx % PW;
    const int ph = (idx / PW) % PH;
    const int d  = (idx / (PW * PH)) % DD;
    const int n  = idx / (PW * PH * DD);

    const float r0 = rois[n * 5 + 0];
    const float r1 = rois[n * 5 + 1];
    const float r2 = rois[n * 5 + 2];
    const float r3 = rois[n * 5 + 3];
    const float r4 = rois[n * 5 + 4];

    const int b = (int)r0;

    const float roi_sw = __fmul_rn(floorf(__fadd_rn(r1, 0.5f)), SCALE);
    const float roi_sh = __fmul_rn(floorf(__fadd_rn(r2, 0.5f)), SCALE);
    const float roi_ew = __fmul_rn(floorf(__fadd_rn(__fadd_rn(r3, 1.0f), 0.5f)), SCALE);
    const float roi_eh = __fmul_rn(floorf(__fadd_rn(__fadd_rn(r4, 1.0f), 0.5f)), SCALE);

    const float roi_w = fmaxf(__fadd_rn(roi_ew, -roi_sw), 0.1f);
    const float roi_h = fmaxf(__fadd_rn(roi_eh, -roi_sh), 0.1f);

    // XLA: divide-by-constant -> multiply-by-reciprocal (f32 rn constant 1/7).
    const float inv7 = 1.0f / 7.0f;   // compile-time correctly-rounded
    const float bin_w = __fmul_rn(roi_w, inv7);
    const float bin_h = __fmul_rn(roi_h, inv7);

    // Separate mul + add (uncontracted), round-to-nearest.
    const float hsf = floorf(__fadd_rn(__fmul_rn((float)ph,       bin_h), roi_sh));
    const float hef = ceilf (__fadd_rn(__fmul_rn((float)(ph + 1), bin_h), roi_sh));
    const float wsf = floorf(__fadd_rn(__fmul_rn((float)pw,       bin_w), roi_sw));
    const float wef = ceilf (__fadd_rn(__fmul_rn((float)(pw + 1), bin_w), roi_sw));

    const int hs = (int)fminf(fmaxf(hsf, 0.0f), (float)HH);
    const int he = (int)fminf(fmaxf(hef, 0.0f), (float)HH);
    const int ws = (int)fminf(fmaxf(wsf, 0.0f), (float)WW);
    const int we = (int)fminf(fmaxf(wef, 0.0f), (float)WW);

    const int area = (he - hs) * (we - ws);
    if (area <= 0) { out[idx] = 0.0f; return; }

    const int c = (d * PH + ph) * PW + pw;
    const float* __restrict__ plane = in + ((size_t)(b * CHN + c)) * (HH * WW);

    float sum = 0.0f;
    for (int h = hs; h < he; ++h) {
        const float* __restrict__ row = plane + h * WW;
        float rsum = 0.0f;
        #pragma unroll 4
        for (int w = ws; w < we; ++w) {
            rsum += row[w];
        }
        sum += rsum;
    }

    out[idx] = __fdiv_rn(sum, (float)area);
}

extern "C" void kernel_launch(void* const* d_in, const int* in_sizes, int n_in,
                              void* d_out, int out_size) {
    const float* input = (const float*)d_in[0];   // (4,1029,80,80) f32
    const float* rois  = (const float*)d_in[1];   // (1024,5) f32
    float* out = (float*)d_out;                   // (1024,21,7,7) f32

    const int total = NROI * DD * PH * PW;
    psroi_direct_kernel<<<(total + 255) / 256, 256>>>(input, rois, out);
}